// round 17
// baseline (speedup 1.0000x reference)
#include <cuda_runtime.h>
#include <cuda_bf16.h>

// Problem shape (fixed by the dataset): B=16, N=2048, NUM_BUCKETS=128
#define BB      16
#define NN      2048
#define NBUCK   128
#define THREADS 256
#define RPB     8                 // rows per block, i-stride 4 (same i mod 4)
#define VPT     2                 // float4 chunks per thread per row: 2048/(256*4)

// out[b,i,j] = pos_w[N-1 + j - i] + ts_w[bucket(b,i,j)]
// bucket = trunc( logf(max(|td|,1)) / 0.301f ), td = ts[min(i+1,N-1)] - ts[j] (j<=i), else 0.
// td < 1e7 -> max bucket 53. Integer form: bucket(d) = #{k>=1 : T_k <= d},
// T_k = min{d : logf((float)d)/0.301f >= k}; <=3 thresholds per octave ->
// bucket(d) = lut[e].base + (d>=t1)+(d>=t2)+(d>=t3), e = ilog2(d).
// ts sorted => within a 4-chunk d0>=d3 -> uniform iff d3 >= T_{b0}.
// R14 post-mortem: occ fixed (77%), issue 74% binds again. This round:
// (a) upper triangle becomes a pure smem copy via precomputed s_posb = pos+tw0
//     (removes 4 FADD per upper chunk, ~50% of all chunks);
// (b) 8 blocks/SM (32-reg cap, already met) -> 100% theoretical occupancy.
__global__ __launch_bounds__(THREADS, 8)
void bias_kernel(const int*   __restrict__ ts,      // int32 [B,N]
                 const float* __restrict__ ts_w,    // [129]
                 const float* __restrict__ pos_w,   // [2N-1]
                 float*       __restrict__ out)     // [B,N,N] fp32
{
    __shared__ __align__(16) float s_pos [2080]; // pos window for this block's 8 rows
    __shared__ __align__(16) float s_posb[2080]; // pos + ts_w[0] (upper-triangle copy src)
    __shared__ int   s_T[64];                    // thresholds: T_0=1, T_1..T_53
    __shared__ int4  s_lut[24];                  // per-exponent {base, t1, t2, t3}
    __shared__ float s_tsw[NBUCK + 1];
    __shared__ int   s_tsn[RPB];

    const int t   = threadIdx.x;
    const int blk = blockIdx.x;                  // 0..255
    const int b   = blockIdx.y;
    // Rows: base + 4r, r=0..7.  base mod 4 constant within block.
    const int base = (blk & 3) + (blk >> 2) * 32;
    const int o7   = 2047 - base - 28;           // pos_w offset of staged window start
    const int* tsrow = ts + (size_t)b * NN;

    // ---- thresholds: exact match of precise logf(x)/0.301f bucketization ----
    if (t <= 53) {
        if (t == 0) {
            s_T[0] = 1;
        } else {
            const float k = (float)t;
            int d = (int)ceilf(expf(0.301f * k));
            if (d < 2) d = 2;
            #pragma unroll 1
            while (d > 2 && (logf((float)(d - 1)) / 0.301f) >= k) d--;
            #pragma unroll 1
            while ((logf((float)d) / 0.301f) < k) d++;
            s_T[t] = d;
        }
    }
    if (t >= 54 && t < 64) s_T[t] = 0x7FFFFFFF;  // sentinel
    if (t <= NBUCK) s_tsw[t] = ts_w[t];
    if (t < RPB) {
        int i = base + 4 * t;
        s_tsn[t] = tsrow[(i < NN - 1) ? (i + 1) : (NN - 1)];
    }

    // ---- stage pos window (2076 floats) and its +tw0 copy, coalesced ----
    const float tw0g = __ldg(ts_w);              // ts_w[0]
    #pragma unroll
    for (int x = t; x < 2076; x += THREADS) {
        const float pw = pos_w[o7 + x];
        s_pos [x] = pw;
        s_posb[x] = pw + tw0g;
    }

    // Register-cache this thread's 8 timestamps as int4 (4 consecutive j per chunk).
    int4 tsd[VPT];
    const int4* tsrow4 = (const int4*)tsrow;
    #pragma unroll
    for (int v = 0; v < VPT; v++)
        tsd[v] = tsrow4[t + v * THREADS];

    __syncthreads();

    if (t < 24) {
        const int lo = 1 << t;
        int cnt = 0;
        #pragma unroll
        for (int k = 1; k <= 53; k++) cnt += (s_T[k] <= lo) ? 1 : 0;
        int4 q;
        q.x = cnt;
        q.y = (cnt + 1 <= 53) ? s_T[cnt + 1] : 0x7FFFFFFF;
        q.z = (cnt + 2 <= 53) ? s_T[cnt + 2] : 0x7FFFFFFF;
        q.w = (cnt + 3 <= 53) ? s_T[cnt + 3] : 0x7FFFFFFF;
        s_lut[t] = q;
    }
    __syncthreads();

    // Single 64-bit base; all row/chunk offsets become compile-time immediates.
    float* const outb = out + ((size_t)b * NN + base) * (size_t)NN;

    #pragma unroll
    for (int v = 0; v < VPT; v++) {
        const int j0 = 4 * (t + v * THREADS);         // warp: 128 consecutive j
        float* const op = outb + j0;                  // row stores at op + r*4*NN (imm)
        const float* const pp  = &s_pos [28 + j0];    // row loads at pp  - 4*r (imm)
        const float* const ppb = &s_posb[28 + j0];
        const int4 td = tsd[v];

        #pragma unroll
        for (int r = 0; r < RPB; r++) {
            const int i   = base + 4 * r;
            const int tsn = s_tsn[r];

            float4 rv;
            if (j0 > i) {
                // strictly upper triangle: bucket 0 -> precomputed pos+tw0 copy
                rv = *(const float4*)(ppb - 4 * r);   // aligned LDS.128
            } else {
                const float4 p = *(const float4*)(pp - 4 * r);
                // one full bucket compute (d0), then a single threshold test for d3:
                // d3 <= d0, so bucket(d3)==bucket(d0) iff d3 >= T_{b0}.
                const int d0 = max(tsn - td.x, 1);
                const int d3 = max(tsn - td.w, 1);
                const int4 q0 = s_lut[31 - __clz(d0)];
                const int b0 = q0.x + (d0 >= q0.y) + (d0 >= q0.z) + (d0 >= q0.w);
                if (d3 >= s_T[b0]) {
                    // bucket uniform across the chunk (common case)
                    const float w = s_tsw[b0];
                    rv.x = p.x + w;
                    rv.y = p.y + w;
                    rv.z = p.z + w;
                    rv.w = p.w + w;
                } else {
                    const int d1 = max(tsn - td.y, 1);
                    const int d2 = max(tsn - td.z, 1);
                    const int4 q1 = s_lut[31 - __clz(d1)];
                    const int4 q2 = s_lut[31 - __clz(d2)];
                    const int4 q3 = s_lut[31 - __clz(d3)];
                    const int b1 = q1.x + (d1 >= q1.y) + (d1 >= q1.z) + (d1 >= q1.w);
                    const int b2 = q2.x + (d2 >= q2.y) + (d2 >= q2.z) + (d2 >= q2.w);
                    const int b3 = q3.x + (d3 >= q3.y) + (d3 >= q3.z) + (d3 >= q3.w);
                    rv.x = p.x + s_tsw[b0];
                    rv.y = p.y + s_tsw[b1];
                    rv.z = p.z + s_tsw[b2];
                    rv.w = p.w + s_tsw[b3];
                }
            }
            // streaming store (write-once data, evict-first), coalesced STG.128
            __stcs((float4*)(op + r * 4 * NN), rv);
        }
    }
}

extern "C" void kernel_launch(void* const* d_in, const int* in_sizes, int n_in,
                              void* d_out, int out_size)
{
    const int*   ts    = (const int*)d_in[0];    // int32 [16,2048]
    const float* ts_w  = (const float*)d_in[1];  // [129]
    const float* pos_w = (const float*)d_in[2];  // [4095]
    float*       out   = (float*)d_out;          // [16,2048,2048] fp32

    dim3 grid(NN / RPB, BB);
    bias_kernel<<<grid, THREADS>>>(ts, ts_w, pos_w, out);
}